// round 4
// baseline (speedup 1.0000x reference)
#include <cuda_runtime.h>
#include <cuda_fp16.h>

typedef unsigned int u32;

#define H 512
#define W 512
#define PLANE (H * W)
#define NPLANES 64          // 32 pred + 32 true planes (channel 1 only)
#define RB 8                // output rows per warp
#define BANDS (H / RB)      // 64
#define STRIPS 2            // 256 cols per warp (8 cols/lane)
#define KSTEPS (RB + 4)     // 12 pipeline steps
#define NBLOCKS (NPLANES * BANDS * STRIPS / 4)   // 2048 blocks of 128 thr

#define PINF2 0x7C007C00u
#define NINF2 0xFC00FC00u

__device__ __half g_bufA[(size_t)NPLANES * PLANE];   // 32 MB
__device__ __half g_bufB[(size_t)NPLANES * PLANE];   // 32 MB
__device__ double g_acc[4];  // cross_pred, sum_pred, cross_true, sum_true

__device__ __forceinline__ u32 h2min(u32 a, u32 b) {
    __half2 r = __hmin2(*reinterpret_cast<__half2*>(&a),
                        *reinterpret_cast<__half2*>(&b));
    return *reinterpret_cast<u32*>(&r);
}
__device__ __forceinline__ u32 h2max(u32 a, u32 b) {
    __half2 r = __hmax2(*reinterpret_cast<__half2*>(&a),
                        *reinterpret_cast<__half2*>(&b));
    return *reinterpret_cast<u32*>(&r);
}
__device__ __forceinline__ u32 h2sub(u32 a, u32 b) {
    __half2 r = __hsub2(*reinterpret_cast<__half2*>(&a),
                        *reinterpret_cast<__half2*>(&b));
    return *reinterpret_cast<u32*>(&r);
}
__device__ __forceinline__ u32 pk(float lo, float hi) {
    __half2 r = __floats2half2_rn(lo, hi);
    return *reinterpret_cast<u32*>(&r);
}
__device__ __forceinline__ float2 up(u32 v) {
    return __half22float2(*reinterpret_cast<__half2*>(&v));
}

// One soft-skeletonize iteration, vertical-first separable pipeline in regs.
// MODE 0: fp32 strided input -> half state.  MODE 1: half -> half.
// MODE 2: half -> fused reduction (no store).
template <int MODE>
__global__ void __launch_bounds__(128) skel_kernel(
    const float* __restrict__ pred, const float* __restrict__ tru, int it)
{
    const int lane  = threadIdx.x & 31;
    const int gw    = blockIdx.x * 4 + (threadIdx.x >> 5);
    const int strip = gw & 1;
    const int band  = (gw >> 1) & (BANDS - 1);
    const int p     = gw >> 7;
    const int rbase = band * RB;
    const int cb    = strip * 256 + lane * 8;
    const int b     = p & 31;

    const float* chan = (p < 32 ? pred : tru) + (size_t)(2 * b + 1) * PLANE;
    const float* oth  = (p < 32 ? tru : pred) + (size_t)(2 * b + 1) * PLANE;
    const __half* srcH = ((it & 1) ? g_bufA : g_bufB) + (size_t)p * PLANE;
    __half*       dstH = ((it & 1) ? g_bufB : g_bufA) + (size_t)p * PLANE;

    const bool edgeL = (lane == 0  && strip == 1);  // halo at cols 254..255
    const bool edgeR = (lane == 31 && strip == 0);  // halo at cols 256..257

    u32 xr[4][4];    // x rows ring   (slot = (r - rbase + 2) & 3)
    u32 xer[4];      // edge halo half2 ring
    u32 mr[4][4];    // min-pool rows ring (slot = k & 3)
    u32 mer[4];      // edge min-pool scalar ring (lo half)
    float accC = 0.f, accS = 0.f;

#pragma unroll
    for (int s = 2; s < 4; ++s) {
        xr[s][0] = xr[s][1] = xr[s][2] = xr[s][3] = PINF2;
        xer[s] = PINF2;
    }

    auto loadrow = [&](int r, int s) {
        u32 a0 = PINF2, a1 = PINF2, a2 = PINF2, a3 = PINF2, ae = PINF2;
        if ((unsigned)r < H) {
            if (MODE == 0) {
                const float* row = chan + (size_t)r * W + cb;
                float4 f0 = *reinterpret_cast<const float4*>(row);
                float4 f1 = *reinterpret_cast<const float4*>(row + 4);
                a0 = pk(f0.x, f0.y); a1 = pk(f0.z, f0.w);
                a2 = pk(f1.x, f1.y); a3 = pk(f1.z, f1.w);
                if (edgeL) {
                    float2 e = *reinterpret_cast<const float2*>(row - 2);
                    ae = pk(e.x, e.y);
                } else if (edgeR) {
                    float2 e = *reinterpret_cast<const float2*>(row + 8);
                    ae = pk(e.x, e.y);
                }
            } else {
                const __half* row = srcH + (size_t)r * W + cb;
                uint4 v = *reinterpret_cast<const uint4*>(row);
                a0 = v.x; a1 = v.y; a2 = v.z; a3 = v.w;
                if (edgeL)      ae = *reinterpret_cast<const u32*>(row - 2);
                else if (edgeR) ae = *reinterpret_cast<const u32*>(row + 8);
            }
        }
        xr[s][0] = a0; xr[s][1] = a1; xr[s][2] = a2; xr[s][3] = a3;
        xer[s] = ae;
    };

    loadrow(rbase - 2, 0);

#pragma unroll 1
    for (int kk = 0; kk < KSTEPS; kk += 4) {
        const bool OUT = (kk >= 4);
#pragma unroll
        for (int u = 0; u < 4; ++u) {
            const int k  = kk + u;
            const int s0 = (u + 2) & 3;   // (k-2)&3
            const int s1 = (u + 3) & 3;   // (k-1)&3
            const int s2 = u;             //  k   &3
            const int s3 = (u + 1) & 3;   // (k+1)&3

            loadrow(rbase - 1 + k, s3);   // prefetch (used next step)

            // ---- min-pool row rm = rbase-3+k  (x rows rm-1..rm+1 = s0,s1,s2)
            const int rm = rbase - 3 + k;
            u32 v1[4];
#pragma unroll
            for (int i = 0; i < 4; ++i)
                v1[i] = h2min(h2min(xr[s0][i], xr[s1][i]), xr[s2][i]);
            u32 v1e = h2min(h2min(xer[s0], xer[s1]), xer[s2]);

            u32 prevU = __shfl_up_sync(0xffffffffu, v1[3], 1);
            u32 nxtU  = __shfl_down_sync(0xffffffffu, v1[0], 1);
            if (lane == 0)  prevU = edgeL ? v1e : 0x7C000000u;  // hi = col-1
            if (lane == 31) nxtU  = edgeR ? v1e : 0x00007C00u;  // lo = col+8

            u32 P0 = __byte_perm(prevU, v1[0], 0x5432);
            u32 P1 = __byte_perm(v1[0], v1[1], 0x5432);
            u32 P2 = __byte_perm(v1[1], v1[2], 0x5432);
            u32 P3 = __byte_perm(v1[2], v1[3], 0x5432);
            u32 P4 = __byte_perm(v1[3], nxtU,  0x5432);

            u32 m0 = h2min(h2min(P0, v1[0]), P1);
            u32 m1 = h2min(h2min(P1, v1[1]), P2);
            u32 m2 = h2min(h2min(P2, v1[2]), P3);
            u32 m3 = h2min(h2min(P3, v1[3]), P4);

            // edge scalar min-pool (col 255 for edgeL / col 256 for edgeR)
            u32 vsw = __byte_perm(v1e, v1e, 0x1032);
            u32 me  = h2min(v1e, vsw);
            me = h2min(me, edgeL ? v1[0] : (v1[3] >> 16));

            if ((unsigned)rm >= H) {                 // maxpool pads -inf
                m0 = m1 = m2 = m3 = NINF2; me = NINF2;
            }
            mr[s2][0] = m0; mr[s2][1] = m1; mr[s2][2] = m2; mr[s2][3] = m3;
            mer[s2] = me;

            // ---- output row o = rbase-4+k  (m rows o-1..o+1 = s0,s1,s2)
            if (OUT) {
                const int o = rbase - 4 + k;
                u32 w[4];
#pragma unroll
                for (int i = 0; i < 4; ++i)
                    w[i] = h2max(h2max(mr[s0][i], mr[s1][i]), mr[s2][i]);
                u32 we = h2max(h2max(mer[s0], mer[s1]), mer[s2]);

                u32 prevM = __shfl_up_sync(0xffffffffu, w[3], 1);
                u32 nxtM  = __shfl_down_sync(0xffffffffu, w[0], 1);
                if (lane == 0)  prevM = edgeL ? (we << 16)    : 0xFC000000u;
                if (lane == 31) nxtM  = edgeR ? (we & 0xFFFFu) : 0x0000FC00u;

                u32 Q0 = __byte_perm(prevM, w[0], 0x5432);
                u32 Q1 = __byte_perm(w[0], w[1], 0x5432);
                u32 Q2 = __byte_perm(w[1], w[2], 0x5432);
                u32 Q3 = __byte_perm(w[2], w[3], 0x5432);
                u32 Q4 = __byte_perm(w[3], nxtM, 0x5432);

                u32 d0 = h2max(h2max(Q0, w[0]), Q1);
                u32 d1 = h2max(h2max(Q1, w[1]), Q2);
                u32 d2 = h2max(h2max(Q2, w[2]), Q3);
                u32 d3 = h2max(h2max(Q3, w[3]), Q4);

                // z = relu(x_o - relu(dil - m_o)); x_o = slot s0, m_o = slot s1
                u32 z0 = h2max(h2sub(xr[s0][0], h2max(h2sub(d0, mr[s1][0]), 0u)), 0u);
                u32 z1 = h2max(h2sub(xr[s0][1], h2max(h2sub(d1, mr[s1][1]), 0u)), 0u);
                u32 z2 = h2max(h2sub(xr[s0][2], h2max(h2sub(d2, mr[s1][2]), 0u)), 0u);
                u32 z3 = h2max(h2sub(xr[s0][3], h2max(h2sub(d3, mr[s1][3]), 0u)), 0u);

                if (MODE == 2) {
                    const float* orow = oth + (size_t)o * W + cb;
                    float4 f0 = *reinterpret_cast<const float4*>(orow);
                    float4 f1 = *reinterpret_cast<const float4*>(orow + 4);
                    float2 a0 = up(z0), a1 = up(z1), a2 = up(z2), a3 = up(z3);
                    accC += a0.x * f0.x + a0.y * f0.y + a1.x * f0.z + a1.y * f0.w;
                    accC += a2.x * f1.x + a2.y * f1.y + a3.x * f1.z + a3.y * f1.w;
                    accS += (a0.x + a0.y) + (a1.x + a1.y)
                          + (a2.x + a2.y) + (a3.x + a3.y);
                } else {
                    uint4 st; st.x = z0; st.y = z1; st.z = z2; st.w = z3;
                    *reinterpret_cast<uint4*>(dstH + (size_t)o * W + cb) = st;
                }
            }
        }
    }

    if (MODE == 2) {
#pragma unroll
        for (int s = 16; s; s >>= 1) {
            accC += __shfl_xor_sync(0xffffffffu, accC, s);
            accS += __shfl_xor_sync(0xffffffffu, accS, s);
        }
        __shared__ float sC[4], sS[4];
        const int wi = threadIdx.x >> 5;
        if (lane == 0) { sC[wi] = accC; sS[wi] = accS; }
        __syncthreads();
        if (threadIdx.x == 0) {
            double c = (double)sC[0] + sC[1] + sC[2] + sC[3];
            double s = (double)sS[0] + sS[1] + sS[2] + sS[3];
            const int base = (p < 32) ? 0 : 2;   // p constant within block
            atomicAdd(&g_acc[base],     c);
            atomicAdd(&g_acc[base + 1], s);
        }
    }
}

__global__ void zero_acc()
{
    if (threadIdx.x < 4) g_acc[threadIdx.x] = 0.0;
}

__global__ void finalize_kernel(float* out)
{
    const double SMOOTH = 1.0;
    double tprec = (g_acc[0] + SMOOTH) / (g_acc[1] + SMOOTH);
    double tsens = (g_acc[2] + SMOOTH) / (g_acc[3] + SMOOTH);
    out[0] = (float)(1.0 - 2.0 * (tprec * tsens) / (tprec + tsens));
}

extern "C" void kernel_launch(void* const* d_in, const int* in_sizes, int n_in,
                              void* d_out, int out_size)
{
    const float* pred = (const float*)d_in[0];
    const float* tru  = (const float*)d_in[1];

    zero_acc<<<1, 32>>>();
    skel_kernel<0><<<NBLOCKS, 128>>>(pred, tru, 0);
    for (int it = 1; it < 9; ++it)
        skel_kernel<1><<<NBLOCKS, 128>>>(pred, tru, it);
    skel_kernel<2><<<NBLOCKS, 128>>>(pred, tru, 9);
    finalize_kernel<<<1, 1>>>((float*)d_out);
}

// round 5
// speedup vs baseline: 1.1299x; 1.1299x over previous
#include <cuda_runtime.h>
#include <cuda_fp16.h>

typedef unsigned int u32;

#define H 512
#define W 512
#define PLANE (H * W)
#define NPLANES 64          // 32 pred + 32 true planes (channel 1 only)
#define RB 16               // output rows per warp
#define BANDS (H / RB)      // 32
#define STRIPS 2            // 256 cols per warp (8 cols/lane)
#define KSTEPS (RB + 4)     // 20 pipeline steps
#define NBLOCKS (NPLANES * BANDS * STRIPS / 4)   // 1024 blocks of 128 thr

#define PINF2 0x7C007C00u
#define NINF2 0xFC00FC00u

__device__ __half g_bufA[(size_t)NPLANES * PLANE];   // 32 MB
__device__ __half g_bufB[(size_t)NPLANES * PLANE];   // 32 MB
__device__ double g_acc[4];  // cross_pred, sum_pred, cross_true, sum_true

__device__ __forceinline__ u32 h2min(u32 a, u32 b) {
    __half2 r = __hmin2(*reinterpret_cast<__half2*>(&a),
                        *reinterpret_cast<__half2*>(&b));
    return *reinterpret_cast<u32*>(&r);
}
__device__ __forceinline__ u32 h2max(u32 a, u32 b) {
    __half2 r = __hmax2(*reinterpret_cast<__half2*>(&a),
                        *reinterpret_cast<__half2*>(&b));
    return *reinterpret_cast<u32*>(&r);
}
__device__ __forceinline__ u32 h2sub(u32 a, u32 b) {
    __half2 r = __hsub2(*reinterpret_cast<__half2*>(&a),
                        *reinterpret_cast<__half2*>(&b));
    return *reinterpret_cast<u32*>(&r);
}
__device__ __forceinline__ u32 h2add(u32 a, u32 b) {
    __half2 r = __hadd2(*reinterpret_cast<__half2*>(&a),
                        *reinterpret_cast<__half2*>(&b));
    return *reinterpret_cast<u32*>(&r);
}
__device__ __forceinline__ u32 pk(float lo, float hi) {
    __half2 r = __floats2half2_rn(lo, hi);
    return *reinterpret_cast<u32*>(&r);
}
__device__ __forceinline__ float2 up(u32 v) {
    return __half22float2(*reinterpret_cast<__half2*>(&v));
}
// (a.hi, b.lo) as (lo, hi)
__device__ __forceinline__ u32 mid(u32 a, u32 b) { return __byte_perm(a, b, 0x5432); }
__device__ __forceinline__ u32 swp(u32 a)        { return __byte_perm(a, a, 0x1032); }

// One soft-skeletonize iteration. All cross-lane exchange happens on LOADED
// rows (shuffles prefetched one step ahead); each step is pure lane-local
// half2 ALU dataflow: vmin3 -> hmin(PRMT) -> hmax(PRMT) -> vmax3 -> z.
// Each lane owns 12 x-cols (6 u32): halo 2 each side of its 8 output cols.
// MODE 0: fp32 strided input -> half. MODE 1: half -> half.
// MODE 2: half -> fused reduction (no store).
template <int MODE>
__global__ void __launch_bounds__(128) skel_kernel(
    const float* __restrict__ pred, const float* __restrict__ tru, int it)
{
    const int lane  = threadIdx.x & 31;
    const int gw    = blockIdx.x * 4 + (threadIdx.x >> 5);
    const int strip = gw & 1;
    const int band  = (gw >> 1) & (BANDS - 1);
    const int p     = gw >> 6;
    const int rbase = band * RB;
    const int cb    = strip * 256 + lane * 8;     // first owned column (halfs)
    const int b     = p & 31;

    const float* chan = (p < 32 ? pred : tru) + (size_t)(2 * b + 1) * PLANE;
    const float* oth  = (p < 32 ? tru : pred) + (size_t)(2 * b + 1) * PLANE;
    const __half* srcH = ((it & 1) ? g_bufA : g_bufB) + (size_t)p * PLANE;
    __half*       dstH = ((it & 1) ? g_bufB : g_bufA) + (size_t)p * PLANE;

    const bool eL = (lane == 0  && strip == 1);   // needs LDG halo (cols 254-255)
    const bool eR = (lane == 31 && strip == 0);   // needs LDG halo (cols 256-257)

    u32 xr[4][6];    // x rows ring: [0]=cols cb-2..cb-1, [1..4]=cb..cb+7, [5]=cb+8..cb+9
    u32 hmr[4][4];   // horizontal-max-of-minpool rows ring
    u32 mc[2][4];    // minpool center (4 u32) ring for z
    float accC = 0.f, accS = 0.f;

#pragma unroll
    for (int i = 0; i < 6; ++i) { xr[2][i] = PINF2; xr[3][i] = PINF2; }

    auto loadrow = [&](int r, int s) {
        u32 a0, a1, a2, a3, a4, a5;
        if ((unsigned)r < H) {
            if (MODE == 0) {
                const float* row = chan + (size_t)r * W + cb;
                float4 f0 = *reinterpret_cast<const float4*>(row);
                float4 f1 = *reinterpret_cast<const float4*>(row + 4);
                a1 = pk(f0.x, f0.y); a2 = pk(f0.z, f0.w);
                a3 = pk(f1.x, f1.y); a4 = pk(f1.z, f1.w);
                a0 = __shfl_up_sync(0xffffffffu, a4, 1);
                a5 = __shfl_down_sync(0xffffffffu, a1, 1);
                if (lane == 0) {
                    a0 = PINF2;
                    if (eL) { float2 e = *reinterpret_cast<const float2*>(row - 2); a0 = pk(e.x, e.y); }
                }
                if (lane == 31) {
                    a5 = PINF2;
                    if (eR) { float2 e = *reinterpret_cast<const float2*>(row + 8); a5 = pk(e.x, e.y); }
                }
            } else {
                const __half* row = srcH + (size_t)r * W + cb;
                uint4 v = *reinterpret_cast<const uint4*>(row);
                a1 = v.x; a2 = v.y; a3 = v.z; a4 = v.w;
                a0 = __shfl_up_sync(0xffffffffu, a4, 1);
                a5 = __shfl_down_sync(0xffffffffu, a1, 1);
                if (lane == 0)
                    a0 = eL ? *reinterpret_cast<const u32*>(row - 2) : PINF2;
                if (lane == 31)
                    a5 = eR ? *reinterpret_cast<const u32*>(row + 8) : PINF2;
            }
        } else {
            a0 = a1 = a2 = a3 = a4 = a5 = PINF2;
        }
        xr[s][0] = a0; xr[s][1] = a1; xr[s][2] = a2;
        xr[s][3] = a3; xr[s][4] = a4; xr[s][5] = a5;
    };

    loadrow(rbase - 2, 0);

#pragma unroll 1
    for (int kk = 0; kk < KSTEPS; kk += 4) {
        const bool OUT = (kk >= 4);
#pragma unroll
        for (int u = 0; u < 4; ++u) {
            const int k  = kk + u;
            const int s0 = (u + 2) & 3;   // row rbase-4+k (= output row o)
            const int s1 = (u + 3) & 3;   // row rbase-3+k
            const int s2 = u;             // row rbase-2+k
            const int s3 = (u + 1) & 3;

            loadrow(rbase - 1 + k, s3);   // prefetch, used next step

            // vertical min over 3 x rows (6 u32 wide)
            u32 v[6];
#pragma unroll
            for (int i = 0; i < 6; ++i)
                v[i] = h2min(h2min(xr[s0][i], xr[s1][i]), xr[s2][i]);

            // horizontal min -> minpool row rm = rbase-3+k (ends half-garbage)
            u32 p01 = mid(v[0], v[1]), p12 = mid(v[1], v[2]), p23 = mid(v[2], v[3]);
            u32 p34 = mid(v[3], v[4]), p45 = mid(v[4], v[5]);
            u32 m0 = h2min(h2min(swp(v[0]), v[0]), p01);
            u32 m1 = h2min(h2min(p01, v[1]), p12);
            u32 m2 = h2min(h2min(p12, v[2]), p23);
            u32 m3 = h2min(h2min(p23, v[3]), p34);
            u32 m4 = h2min(h2min(p34, v[4]), p45);
            u32 m5 = h2min(h2min(p45, v[5]), swp(v[5]));

            const int rm = rbase - 3 + k;
            if ((unsigned)rm >= H) {      // maxpool pads -inf for OOB rows
                m0 = m1 = m2 = m3 = m4 = m5 = NINF2;
            }

            // horizontal max of minpool row (center 4 u32)
            u32 q01 = mid(m0, m1), q12 = mid(m1, m2), q23 = mid(m2, m3);
            u32 q34 = mid(m3, m4), q45 = mid(m4, m5);
            hmr[s2][0] = h2max(h2max(q01, m1), q12);
            hmr[s2][1] = h2max(h2max(q12, m2), q23);
            hmr[s2][2] = h2max(h2max(q23, m3), q34);
            hmr[s2][3] = h2max(h2max(q34, m4), q45);

            // stash minpool center for z (consumed next step)
            mc[k & 1][0] = m1; mc[k & 1][1] = m2;
            mc[k & 1][2] = m3; mc[k & 1][3] = m4;

            if (OUT) {
                const int o = rbase - 4 + k;
                // dil = vertical max of 3 hmax rows; z = relu(x - dil + m)
                // (dil >= m always since maxpool window contains center)
                u32 z[4];
#pragma unroll
                for (int i = 0; i < 4; ++i) {
                    u32 dil = h2max(h2max(hmr[s0][i], hmr[s1][i]), hmr[s2][i]);
                    z[i] = h2max(h2add(h2sub(xr[s0][i + 1], dil),
                                       mc[(k + 1) & 1][i]), 0u);
                }
                if (MODE == 2) {
                    const float* orow = oth + (size_t)o * W + cb;
                    float4 f0 = *reinterpret_cast<const float4*>(orow);
                    float4 f1 = *reinterpret_cast<const float4*>(orow + 4);
                    float2 a0 = up(z[0]), a1 = up(z[1]), a2 = up(z[2]), a3 = up(z[3]);
                    accC += a0.x * f0.x + a0.y * f0.y + a1.x * f0.z + a1.y * f0.w;
                    accC += a2.x * f1.x + a2.y * f1.y + a3.x * f1.z + a3.y * f1.w;
                    accS += (a0.x + a0.y) + (a1.x + a1.y)
                          + (a2.x + a2.y) + (a3.x + a3.y);
                } else {
                    uint4 st; st.x = z[0]; st.y = z[1]; st.z = z[2]; st.w = z[3];
                    *reinterpret_cast<uint4*>(dstH + (size_t)o * W + cb) = st;
                }
            }
        }
    }

    if (MODE == 2) {
#pragma unroll
        for (int s = 16; s; s >>= 1) {
            accC += __shfl_xor_sync(0xffffffffu, accC, s);
            accS += __shfl_xor_sync(0xffffffffu, accS, s);
        }
        __shared__ float sC[4], sS[4];
        const int wi = threadIdx.x >> 5;
        if (lane == 0) { sC[wi] = accC; sS[wi] = accS; }
        __syncthreads();
        if (threadIdx.x == 0) {
            double c = (double)sC[0] + sC[1] + sC[2] + sC[3];
            double s = (double)sS[0] + sS[1] + sS[2] + sS[3];
            const int base = (p < 32) ? 0 : 2;   // p constant within block
            atomicAdd(&g_acc[base],     c);
            atomicAdd(&g_acc[base + 1], s);
        }
    }
}

__global__ void zero_acc()
{
    if (threadIdx.x < 4) g_acc[threadIdx.x] = 0.0;
}

__global__ void finalize_kernel(float* out)
{
    const double SMOOTH = 1.0;
    double tprec = (g_acc[0] + SMOOTH) / (g_acc[1] + SMOOTH);
    double tsens = (g_acc[2] + SMOOTH) / (g_acc[3] + SMOOTH);
    out[0] = (float)(1.0 - 2.0 * (tprec * tsens) / (tprec + tsens));
}

extern "C" void kernel_launch(void* const* d_in, const int* in_sizes, int n_in,
                              void* d_out, int out_size)
{
    const float* pred = (const float*)d_in[0];
    const float* tru  = (const float*)d_in[1];

    zero_acc<<<1, 32>>>();
    skel_kernel<0><<<NBLOCKS, 128>>>(pred, tru, 0);
    for (int it = 1; it < 9; ++it)
        skel_kernel<1><<<NBLOCKS, 128>>>(pred, tru, it);
    skel_kernel<2><<<NBLOCKS, 128>>>(pred, tru, 9);
    finalize_kernel<<<1, 1>>>((float*)d_out);
}